// round 5
// baseline (speedup 1.0000x reference)
#include <cuda_runtime.h>
#include <cstdint>

// CapsuleRouting load-once cluster scheme:
//  - unit = (b, x-tile of 4); cluster of 8 CTAs, CTA holds 18 B-values in smem
//  - u read from DRAM exactly once (170 MB total vs 510 MB streaming)
//  - r register-resident (9/thread); softmax via 16-lane shuffles
//  - per-pass cross-CTA s-reduction via DSMEM (owner rank = C>>1), 2 cluster syncs

#define C_N    16
#define P_N    16
#define F2     144
#define XT     4
#define NTILE  36            // 144 / XT
#define CLUSTER 8
#define BSL    18            // B per CTA
#define UPLANE 68            // 16p*4x + 4 pad (272B, 16B-aligned)

#define U_FL     (BSL * C_N * UPLANE)     // 19584
#define V_OFF    U_FL
#define V_FL     (C_N * UPLANE)           // 1088
#define RECV_OFF (V_OFF + V_FL)
#define RECV_FL  (16 * 2 * 4 * 16)        // 2048 : [contrib16][Cco2][z4][p16]
#define SMEM_FL  (RECV_OFF + RECV_FL)     // 22720
#define SMEM_BYTES (SMEM_FL * 4)          // 90880  -> 2 CTAs/SM

#define V_ELEMS (8 * C_N * P_N * F2)      // 294912

__device__ __forceinline__ void cp_async16(uint32_t s, const float* g) {
    asm volatile("cp.async.cg.shared.global [%0], [%1], 16;" :: "r"(s), "l"(g));
}
__device__ __forceinline__ uint32_t mapa_u32(uint32_t a, uint32_t r) {
    uint32_t o;
    asm("mapa.shared::cluster.u32 %0, %1, %2;" : "=r"(o) : "r"(a), "r"(r));
    return o;
}
__device__ __forceinline__ void st_clu_v4(uint32_t a, float x, float y, float z, float w) {
    asm volatile("st.shared::cluster.v4.f32 [%0], {%1,%2,%3,%4};"
                 :: "r"(a), "f"(x), "f"(y), "f"(z), "f"(w) : "memory");
}
__device__ __forceinline__ void st_clu_f32(uint32_t a, float v) {
    asm volatile("st.shared::cluster.f32 [%0], %1;" :: "r"(a), "f"(v) : "memory");
}
#define CLUSTER_SYNC() do { \
    asm volatile("barrier.cluster.arrive.aligned;" ::: "memory"); \
    asm volatile("barrier.cluster.wait.aligned;"   ::: "memory"); } while (0)

__global__ void __cluster_dims__(CLUSTER, 1, 1) __launch_bounds__(128, 2)
caps_cluster_kernel(const float* __restrict__ u, float* __restrict__ out) {
    extern __shared__ float sm[];
    const uint32_t smb = (uint32_t)__cvta_generic_to_shared(sm);
    const int t = threadIdx.x;
    uint32_t rank;
    asm("mov.u32 %0, %%cluster_ctarank;" : "=r"(rank));

    const unsigned unit = blockIdx.x / CLUSTER;   // b-major: adjacent tiles co-resident
    const int b    = unit / NTILE;
    const int tile = unit % NTILE;
    const int x0   = tile * XT;

    const float* ub = u + (size_t)b * 144 * C_N * P_N * F2;
    const int B0 = (int)rank * BSL;

    // ---- load slice once: 18*16*16 rows of 16B (4608 rows / 128 threads)
#pragma unroll
    for (int k = 0; k < 36; k++) {
        int q  = t + k * 128;
        int Bl = q >> 8, Cl = (q >> 4) & 15, pl = q & 15;
        const float* g = ub + (((size_t)(B0 + Bl) * C_N + Cl) * P_N + pl) * F2 + x0;
        cp_async16(smb + 4u * ((Bl * C_N + Cl) * UPLANE + pl * 4), g);
    }
    asm volatile("cp.async.commit_group;");
    asm volatile("cp.async.wait_group 0;");
    __syncthreads();

    // compute mapping: t = (Bp*4 + z)*16 + Cc  (C in 16-lane shuffle groups)
    const int Cc = t & 15;
    const int qq = t >> 4;
    const int z  = qq & 3;
    const int Bp = qq >> 2;          // handles Bl = Bp*9 + j, j<9

    float r9[9];

#pragma unroll 1
    for (int pass = 0; pass < 3; pass++) {
        float vreg[16];
        if (pass) {
#pragma unroll
            for (int p = 0; p < 16; p++) vreg[p] = sm[V_OFF + Cc * UPLANE + p * 4 + z];
        }
        float sreg[16];
#pragma unroll
        for (int p = 0; p < 16; p++) sreg[p] = 0.f;

#pragma unroll
        for (int j = 0; j < 9; j++) {
            const float* base = sm + ((Bp * 9 + j) * C_N + Cc) * UPLANE + z;
            float ureg[16];
#pragma unroll
            for (int p = 0; p < 16; p++) ureg[p] = base[p * 4];

            if (pass == 0) {
#pragma unroll
                for (int p = 0; p < 16; p++) sreg[p] += ureg[p];
            } else {
                float dot = 0.f;
#pragma unroll
                for (int p = 0; p < 16; p++) dot = fmaf(ureg[p], vreg[p], dot);
                float rv = (pass == 1) ? dot : (r9[j] + dot);
                r9[j] = rv;
                // softmax over C (no max-subtraction; |rv| small)
                float e = __expf(rv), ss = e;
#pragma unroll
                for (int m = 1; m < 16; m <<= 1)
                    ss += __shfl_xor_sync(0xffffffffu, ss, m);
                float cc = __fdividef(e, ss);
#pragma unroll
                for (int p = 0; p < 16; p++) sreg[p] = fmaf(cc, ureg[p], sreg[p]);
            }
        }
        if (pass == 0) {
#pragma unroll
            for (int p = 0; p < 16; p++) sreg[p] *= 0.0625f;   // uniform c = 1/16
        }

        // ---- send partial s[16p] for (Cc, z) to owner rank = Cc>>1 via DSMEM
        {
            uint32_t loc = smb + 4u * (RECV_OFF +
                             ((((int)rank * 2 + Bp) * 2 + (Cc & 1)) * 4 + z) * 16);
            uint32_t rad = mapa_u32(loc, (uint32_t)(Cc >> 1));
            st_clu_v4(rad,      sreg[0],  sreg[1],  sreg[2],  sreg[3]);
            st_clu_v4(rad + 16, sreg[4],  sreg[5],  sreg[6],  sreg[7]);
            st_clu_v4(rad + 32, sreg[8],  sreg[9],  sreg[10], sreg[11]);
            st_clu_v4(rad + 48, sreg[12], sreg[13], sreg[14], sreg[15]);
        }
        CLUSTER_SYNC();   // release sends / acquire for owner reads

        // ---- owner reduce + squash: this CTA owns C = 2*rank + Cco
        {
            const int Cco = t >> 6, z2 = (t >> 4) & 3, p2 = t & 15;
            float s = 0.f;
#pragma unroll
            for (int k2 = 0; k2 < 16; k2++)
                s += sm[RECV_OFF + ((k2 * 2 + Cco) * 4 + z2) * 16 + p2];
            float sn = s * s;
#pragma unroll
            for (int m = 1; m < 16; m <<= 1)
                sn += __shfl_xor_sync(0xffffffffu, sn, m);
            const float scale = sqrtf(sn) / (1.f + sn);
            const float vv = s * scale;
            const int Cg = (int)rank * 2 + Cco;

            if (pass < 2) {
                // broadcast v element to all 8 CTAs' v_s
                uint32_t loc = smb + 4u * (V_OFF + Cg * UPLANE + p2 * 4 + z2);
#pragma unroll
                for (int k2 = 0; k2 < 8; k2++)
                    st_clu_f32(mapa_u32(loc, (uint32_t)k2), vv);
            } else {
                out[(((size_t)(b * C_N + Cg)) * P_N + p2) * F2 + x0 + z2] = vv;
                if (p2 == 0)
                    out[(size_t)V_ELEMS + ((size_t)(b * C_N + Cg)) * F2 + x0 + z2] =
                        sn / (1.f + sn);
            }
        }
        if (pass < 2) CLUSTER_SYNC();   // v visible before next pass reads it
    }
    CLUSTER_SYNC();   // no CTA exits while peers' DSMEM window could be open
}

extern "C" void kernel_launch(void* const* d_in, const int* in_sizes, int n_in,
                              void* d_out, int out_size) {
    const float* u = (const float*)d_in[0];   // (8,144,16,16,12,12) f32
    float* out = (float*)d_out;               // v (8,16,16,144) then a_out (8,16,144)

    cudaFuncSetAttribute(caps_cluster_kernel,
                         cudaFuncAttributeMaxDynamicSharedMemorySize, SMEM_BYTES);
    caps_cluster_kernel<<<8 * NTILE * CLUSTER, 128, SMEM_BYTES>>>(u, out);
}